// round 15
// baseline (speedup 1.0000x reference)
#include <cuda_runtime.h>
#include <cuda_bf16.h>

#define WEIGHT_POSITIVE 0.1f

// Over-decomposed: 4 waves of 8 CTAs/SM. Early-finishing SMs pick up
// next-wave CTAs, averaging out per-SM speed variance (L2 die distance)
// instead of letting one slow SM bind the whole kernel.
static constexpr int BLOCKS  = 148 * 32;   // 4736
static constexpr int THREADS = 256;

// Scratch (no device allocation allowed anywhere).
__device__ float        g_partials[BLOCKS];
__device__ unsigned int g_ticket = 0;

__device__ __forceinline__ float elem(float p, int t)
{
    float d   = p - (float)t;
    bool  mis = (p >= 0.5f) != (t == 1);
    return (mis ? (1.0f + WEIGHT_POSITIVE) : 1.0f) * d * d;
}

__global__ __launch_bounds__(THREADS)
void wmse_fused_kernel(const float4* __restrict__ pred4,
                       const int4*   __restrict__ tgt4,
                       float* __restrict__ out,
                       int n_vec, float inv_n)
{
    const int stride = gridDim.x * blockDim.x;

    float sum = 0.0f;
    for (int i = blockIdx.x * blockDim.x + threadIdx.x; i < n_vec; i += stride) {
        float4 p = __ldg(&pred4[i]);
        int4   t = __ldg(&tgt4[i]);
        sum += elem(p.x, t.x) + elem(p.y, t.y) + elem(p.z, t.z) + elem(p.w, t.w);
    }

    // Warp reduce
    #pragma unroll
    for (int off = 16; off > 0; off >>= 1)
        sum += __shfl_down_sync(0xFFFFFFFFu, sum, off);

    __shared__ float warp_sums[THREADS / 32];
    __shared__ bool  is_last;
    int lane = threadIdx.x & 31;
    int wid  = threadIdx.x >> 5;
    if (lane == 0) warp_sums[wid] = sum;
    __syncthreads();

    if (wid == 0) {
        float s = (lane < THREADS / 32) ? warp_sums[lane] : 0.0f;
        #pragma unroll
        for (int off = 16; off > 0; off >>= 1)
            s += __shfl_down_sync(0xFFFFFFFFu, s, off);
        if (lane == 0) {
            g_partials[blockIdx.x] = s;
            __threadfence();
            unsigned int t = atomicAdd(&g_ticket, 1u);
            is_last = (t == (unsigned int)(gridDim.x - 1));
        }
    }
    __syncthreads();

    // Last block sums all partials in a FIXED order -> deterministic.
    if (is_last) {
        float fs = 0.0f;
        for (int k = threadIdx.x; k < BLOCKS; k += THREADS)
            fs += *((volatile float*)&g_partials[k]);

        #pragma unroll
        for (int off = 16; off > 0; off >>= 1)
            fs += __shfl_down_sync(0xFFFFFFFFu, fs, off);

        if (lane == 0) warp_sums[wid] = fs;
        __syncthreads();

        if (wid == 0) {
            float s = (lane < THREADS / 32) ? warp_sums[lane] : 0.0f;
            #pragma unroll
            for (int off = 16; off > 0; off >>= 1)
                s += __shfl_down_sync(0xFFFFFFFFu, s, off);
            if (lane == 0) {
                out[0] = s * inv_n;
                g_ticket = 0;   // reset for next graph replay (deterministic)
            }
        }
    }
}

extern "C" void kernel_launch(void* const* d_in, const int* in_sizes, int n_in,
                              void* d_out, int out_size)
{
    const float* pred = (const float*)d_in[0];
    const int*   tgt  = (const int*)d_in[1];
    float*       out  = (float*)d_out;
    int n = in_sizes[0];

    int n_vec = n / 4;  // N = 2^25, divisible by 4

    wmse_fused_kernel<<<BLOCKS, THREADS>>>((const float4*)pred, (const int4*)tgt,
                                           out, n_vec, 1.0f / (float)n);
}

// round 16
// speedup vs baseline: 1.1654x; 1.1654x over previous
#include <cuda_runtime.h>
#include <cuda_bf16.h>
#include <cstdint>

#define WEIGHT_POSITIVE 0.1f

static constexpr int THREADS   = 256;
static constexpr int BLOCKS    = 148 * 2;          // 296: 2 CTAs/SM (best measured)
static constexpr int TILE_V4   = 512;              // 512 float4 = 8KB per array per tile
static constexpr int TILE_B    = TILE_V4 * 16;     // 8192 bytes
static constexpr int DEPTH     = 4;                // best measured pipeline depth

static constexpr int SM_MBAR   = 0;
static constexpr int SM_PRED   = 128;
static constexpr int SM_TGT    = SM_PRED + DEPTH * TILE_B;
static constexpr int SMEM_SIZE = SM_TGT + DEPTH * TILE_B;   // 128 + 64KB

// Scratch (no device allocation allowed anywhere).
__device__ float        g_partials[BLOCKS];
__device__ unsigned int g_ticket = 0;

__device__ __forceinline__ float elem(float p, int t)
{
    float d   = p - (float)t;
    bool  mis = (p >= 0.5f) != (t == 1);
    return (mis ? (1.0f + WEIGHT_POSITIVE) : 1.0f) * d * d;
}

__device__ __forceinline__ float quad(float4 p, int4 t)
{
    return (elem(p.x, t.x) + elem(p.y, t.y)) + (elem(p.z, t.z) + elem(p.w, t.w));
}

__device__ __forceinline__ void mbar_init(uint32_t addr, uint32_t count)
{
    asm volatile("mbarrier.init.shared.b64 [%0], %1;" :: "r"(addr), "r"(count) : "memory");
}

__device__ __forceinline__ void mbar_expect_tx(uint32_t addr, uint32_t bytes)
{
    asm volatile("mbarrier.arrive.expect_tx.shared.b64 _, [%0], %1;"
                 :: "r"(addr), "r"(bytes) : "memory");
}

__device__ __forceinline__ void mbar_wait(uint32_t addr, uint32_t parity)
{
    asm volatile(
        "{\n\t"
        ".reg .pred P;\n\t"
        "WAIT_%=:\n\t"
        "mbarrier.try_wait.parity.acquire.cta.shared::cta.b64 P, [%0], %1, 0x989680;\n\t"
        "@P bra.uni DONE_%=;\n\t"
        "bra.uni WAIT_%=;\n\t"
        "DONE_%=:\n\t"
        "}"
        :: "r"(addr), "r"(parity) : "memory");
}

__device__ __forceinline__ void bulk_copy(uint32_t smem_dst, const void* gmem_src,
                                          uint32_t bytes, uint32_t mbar)
{
    asm volatile(
        "cp.async.bulk.shared::cluster.global.mbarrier::complete_tx::bytes "
        "[%0], [%1], %2, [%3];"
        :: "r"(smem_dst), "l"(gmem_src), "r"(bytes), "r"(mbar) : "memory");
}

// Release-scoped ticket: makes this CTA's prior global writes (its partial)
// visible before the counter increment lands. Much cheaper than __threadfence.
__device__ __forceinline__ unsigned int ticket_release_add(unsigned int* addr)
{
    unsigned int old;
    asm volatile("atom.release.gpu.global.add.u32 %0, [%1], 1;"
                 : "=r"(old) : "l"(addr) : "memory");
    return old;
}

__global__ __launch_bounds__(THREADS)
void wmse_bulk_kernel(const float4* __restrict__ pred4,
                      const int4*   __restrict__ tgt4,
                      float* __restrict__ out,
                      int n_tiles, float inv_n)
{
    extern __shared__ char smem[];
    const uint32_t sbase = (uint32_t)__cvta_generic_to_shared(smem);
    const int tid = threadIdx.x;

    // Interleaved tile ownership (round-robin by gridDim) — empirically the
    // ordering DRAM likes best.
    int my_tiles = (n_tiles - (int)blockIdx.x + (int)gridDim.x - 1) / (int)gridDim.x;

    if (tid == 0) {
        #pragma unroll
        for (int s = 0; s < DEPTH; s++)
            mbar_init(sbase + SM_MBAR + s * 8, 1);
    }
    __syncthreads();

    // Prologue: issue first DEPTH tiles.
    if (tid == 0) {
        #pragma unroll
        for (int s = 0; s < DEPTH; s++) {
            if (s < my_tiles) {
                long g = (long)blockIdx.x + (long)s * gridDim.x;
                uint32_t mb = sbase + SM_MBAR + s * 8;
                mbar_expect_tx(mb, 2 * TILE_B);
                bulk_copy(sbase + SM_PRED + s * TILE_B, pred4 + g * TILE_V4, TILE_B, mb);
                bulk_copy(sbase + SM_TGT  + s * TILE_B, tgt4  + g * TILE_V4, TILE_B, mb);
            }
        }
    }

    float sum = 0.0f;
    for (int k = 0; k < my_tiles; k++) {
        int s = k % DEPTH;
        uint32_t ph = (uint32_t)((k / DEPTH) & 1);
        uint32_t mb = sbase + SM_MBAR + s * 8;
        mbar_wait(mb, ph);

        const float4* ps = (const float4*)(smem + SM_PRED + s * TILE_B);
        const int4*   ts = (const int4*)  (smem + SM_TGT  + s * TILE_B);

        float4 p0 = ps[tid];
        float4 p1 = ps[tid + THREADS];
        int4   t0 = ts[tid];
        int4   t1 = ts[tid + THREADS];
        sum += quad(p0, t0) + quad(p1, t1);

        __syncthreads();   // all reads of slot s done before refill

        if (tid == 0 && k + DEPTH < my_tiles) {
            long g = (long)blockIdx.x + (long)(k + DEPTH) * gridDim.x;
            mbar_expect_tx(mb, 2 * TILE_B);
            bulk_copy(sbase + SM_PRED + s * TILE_B, pred4 + g * TILE_V4, TILE_B, mb);
            bulk_copy(sbase + SM_TGT  + s * TILE_B, tgt4  + g * TILE_V4, TILE_B, mb);
        }
    }

    // Warp reduce
    #pragma unroll
    for (int off = 16; off > 0; off >>= 1)
        sum += __shfl_down_sync(0xFFFFFFFFu, sum, off);

    __shared__ float warp_sums[THREADS / 32];
    __shared__ bool  is_last;
    int lane = tid & 31;
    int wid  = tid >> 5;
    if (lane == 0) warp_sums[wid] = sum;
    __syncthreads();

    if (wid == 0) {
        float s = (lane < THREADS / 32) ? warp_sums[lane] : 0.0f;
        #pragma unroll
        for (int off = 16; off > 0; off >>= 1)
            s += __shfl_down_sync(0xFFFFFFFFu, s, off);
        if (lane == 0) {
            g_partials[blockIdx.x] = s;
            unsigned int t = ticket_release_add(&g_ticket);
            is_last = (t == (unsigned int)(gridDim.x - 1));
        }
    }
    __syncthreads();

    // Last block sums all partials in a FIXED order -> deterministic.
    if (is_last) {
        float fs = 0.0f;
        for (int k = tid; k < BLOCKS; k += THREADS)
            fs += __ldcg(&g_partials[k]);

        #pragma unroll
        for (int off = 16; off > 0; off >>= 1)
            fs += __shfl_down_sync(0xFFFFFFFFu, fs, off);

        if (lane == 0) warp_sums[wid] = fs;
        __syncthreads();

        if (wid == 0) {
            float s = (lane < THREADS / 32) ? warp_sums[lane] : 0.0f;
            #pragma unroll
            for (int off = 16; off > 0; off >>= 1)
                s += __shfl_down_sync(0xFFFFFFFFu, s, off);
            if (lane == 0) {
                out[0] = s * inv_n;
                g_ticket = 0;   // reset for next graph replay
            }
        }
    }
}

extern "C" void kernel_launch(void* const* d_in, const int* in_sizes, int n_in,
                              void* d_out, int out_size)
{
    const float* pred = (const float*)d_in[0];
    const int*   tgt  = (const int*)d_in[1];
    float*       out  = (float*)d_out;
    int n = in_sizes[0];

    int n_vec   = n / 4;            // 2^23 float4s
    int n_tiles = n_vec / TILE_V4;  // 16384 tiles (exact for N = 2^25)

    cudaFuncSetAttribute(wmse_bulk_kernel,
                         cudaFuncAttributeMaxDynamicSharedMemorySize, SMEM_SIZE);

    wmse_bulk_kernel<<<BLOCKS, THREADS, SMEM_SIZE>>>(
        (const float4*)pred, (const int4*)tgt, out, n_tiles, 1.0f / (float)n);
}